// round 3
// baseline (speedup 1.0000x reference)
#include <cuda_runtime.h>
#include <math.h>

#define BB 8
#define TT 2048
#define M_ROWS (BB*TT)   /* 16384 */
#define DVC 1024
#define DAC 128
#define IN_C 1152
#define D1C 512
#define D2C 128
#define DHP 264          /* 257 padded to mult of 8 */
#define DGC 128

/* ---------------- scratch (static device globals; no allocs) ---------------- */
__device__ float g_y1[M_ROWS * D1C];        // 33.5 MB
__device__ float g_xv2[M_ROWS * D2C];       // 8.4 MB
__device__ float g_proj[M_ROWS * DHP];      // 17.3 MB
__device__ float g_qproj[M_ROWS * DHP];     // 17.3 MB
__device__ float g_gwT[256 * DHP];          // gwT[0:128]=gw1^T, [128:256]=gw2^T (zero-padded)
__device__ float g_g12[M_ROWS * 256];       // cols 0..127 = proj@gw1, 128..255 = proj@gw2
__device__ float g_g1T[BB * DGC * TT];      // per-batch transpose of g1
__device__ float g_E[(size_t)BB * TT * TT]; // 134 MB: exp(thr) masked by col
__device__ float g_denom[M_ROWS];
__device__ float g_outx[M_ROWS * 256];      // [x1 | x2]
__device__ float g_frame[M_ROWS];
__device__ float g_scanF[M_ROWS * DGC];

/* ---------------- generic 128x128x8 SGEMM, C = A[M,K] * B[N,K]^T ------------ */
struct GemmP {
    const float* A; const float* Bm; float* C;
    int K, lda, ldb, ldc;
    long aS, bS, cS;            // per-blockIdx.z strides
    const float* bias;
    const int* seq;
    const float* denom;
};

// MODE 0: C = leaky(acc + bias[n])
// MODE 1: C = acc
// MODE 2: similarity epilogue -> E (col-masked exp(thr))
// MODE 3: adj matmul epilogue -> leaky(acc/denom) row-masked
template <int MODE>
__global__ __launch_bounds__(256) void sgemm(GemmP p) {
    __shared__ float As[8][128];
    __shared__ float Bs[8][128];
    const int z = blockIdx.z;
    const float* A  = p.A  + (long)z * p.aS;
    const float* Bm = p.Bm + (long)z * p.bS;
    float*       C  = p.C  + (long)z * p.cS;
    const int tid = threadIdx.x;
    const int tx = tid & 15, ty = tid >> 4;
    const int rowBase = blockIdx.y << 7;
    const int colBase = blockIdx.x << 7;
    const int lr = tid >> 1;
    const int lc = (tid & 1) << 2;
    const float* aPtr = A  + (long)(rowBase + lr) * p.lda + lc;
    const float* bPtr = Bm + (long)(colBase + lr) * p.ldb + lc;

    float acc[8][8];
#pragma unroll
    for (int i = 0; i < 8; i++)
#pragma unroll
        for (int j = 0; j < 8; j++) acc[i][j] = 0.f;

    for (int k0 = 0; k0 < p.K; k0 += 8) {
        float4 av = *(const float4*)(aPtr + k0);
        float4 bv = *(const float4*)(bPtr + k0);
        As[lc + 0][lr] = av.x; As[lc + 1][lr] = av.y;
        As[lc + 2][lr] = av.z; As[lc + 3][lr] = av.w;
        Bs[lc + 0][lr] = bv.x; Bs[lc + 1][lr] = bv.y;
        Bs[lc + 2][lr] = bv.z; Bs[lc + 3][lr] = bv.w;
        __syncthreads();
#pragma unroll
        for (int kk = 0; kk < 8; kk++) {
            float a[8], b[8];
            *(float4*)&a[0] = *(const float4*)&As[kk][ty << 3];
            *(float4*)&a[4] = *(const float4*)&As[kk][(ty << 3) + 4];
            *(float4*)&b[0] = *(const float4*)&Bs[kk][tx << 3];
            *(float4*)&b[4] = *(const float4*)&Bs[kk][(tx << 3) + 4];
#pragma unroll
            for (int i = 0; i < 8; i++)
#pragma unroll
                for (int j = 0; j < 8; j++)
                    acc[i][j] = fmaf(a[i], b[j], acc[i][j]);
        }
        __syncthreads();
    }

    const int L = (MODE >= 2) ? p.seq[z] : 0;
#pragma unroll
    for (int i = 0; i < 8; i++) {
        const int m = rowBase + (ty << 3) + i;
        float inv = 1.0f;
        if (MODE == 3) inv = 1.0f / p.denom[z * TT + m];
#pragma unroll
        for (int j = 0; j < 8; j++) {
            const int n = colBase + (tx << 3) + j;
            float v = acc[i][j];
            if (MODE == 0) {
                v += p.bias[n];
                v = (v >= 0.f) ? v : 0.01f * v;
            } else if (MODE == 2) {
                // xy = -(signed inner product); arccosh via algebra:
                // exp(-log(w)) == 1/w ; both clips provably never bind.
                float xy = fmaxf(-v, 1.0f);
                float w  = xy + sqrtf(xy * xy - 1.0f + 1e-7f);
                float x2v = 1.0f / w;
                float e;
                if (n < L) e = (x2v > 0.8f) ? expf(x2v) : 1.0f;
                else       e = 0.f;
                v = e;
            } else if (MODE == 3) {
                v *= inv;
                v = (v >= 0.f) ? v : 0.01f * v;
                if (m >= L) v = 0.f;
            }
            C[(long)m * p.ldc + n] = v;
        }
    }
}

/* ---------------- small kernels ---------------- */
__global__ void prep_gwT(const float* gw1, const float* gw2, float* gwT) {
    int idx = blockIdx.x * 256 + threadIdx.x;   // 256*264 total
    if (idx >= 256 * DHP) return;
    int r = idx / DHP, k = idx % DHP;
    float v = 0.f;
    if (k < 257) v = (r < 128) ? gw1[k * 128 + r] : gw2[k * 128 + (r - 128)];
    gwT[idx] = v;
}

__global__ void proj_kernel(const float* xv2, const float* inputs,
                            float* proj, float* qproj) {
    const int row = blockIdx.x;
    const int tid = threadIdx.x;  // 256
    float x = (tid < 128) ? xv2[row * 128 + tid]
                          : inputs[(long)row * IN_C + DVC + (tid - 128)];
    __shared__ float red[256];
    red[tid] = x * x;
    __syncthreads();
    for (int st = 128; st > 0; st >>= 1) {
        if (tid < st) red[tid] += red[tid + st];
        __syncthreads();
    }
    float nn = sqrtf(fmaxf(red[0], 1e-12f));
    float sh = sinhf(nn) / nn;
    float* pr = proj  + (long)row * DHP;
    float* qr = qproj + (long)row * DHP;
    float val = sh * x;
    pr[1 + tid] = val;
    qr[1 + tid] = val;
    if (tid == 0) { float ch = coshf(nn); pr[0] = ch; qr[0] = -ch; }
    if (tid < 7)  { pr[257 + tid] = 0.f; qr[257 + tid] = 0.f; }
}

__global__ void transpose_g1(const float* g12, float* g1T) {
    __shared__ float tile[32][33];
    int b = blockIdx.z;
    int t0 = blockIdx.x * 32, n0 = blockIdx.y * 32;
    for (int r = threadIdx.y; r < 32; r += 8)
        tile[r][threadIdx.x] = g12[((long)(b * TT + t0 + r)) * 256 + n0 + threadIdx.x];
    __syncthreads();
    for (int r = threadIdx.y; r < 32; r += 8)
        g1T[(long)b * DGC * TT + (long)(n0 + r) * TT + t0 + threadIdx.x] = tile[threadIdx.x][r];
}

__global__ void rowsum_kernel(const float* E, float* denom) {
    int row = blockIdx.x;
    const float* e = E + (size_t)row * TT;
    float s = 0.f;
    for (int j = threadIdx.x; j < TT; j += 256) s += e[j];
    __shared__ float red[256];
    red[threadIdx.x] = s;
    __syncthreads();
    for (int st = 128; st > 0; st >>= 1) {
        if (threadIdx.x < st) red[threadIdx.x] += red[threadIdx.x + st];
        __syncthreads();
    }
    if (threadIdx.x == 0) denom[row] = red[0];
}

// disadj @ y  via forward + backward exponential scan: r = exp(-1/e)
__global__ void scan_kernel(const float* g12, float* scanF, float* outx) {
    const int b = blockIdx.x;       // 8
    const int c = threadIdx.x;      // 128
    const float r = 0.69220062755534635f;  // exp(-exp(-1))
    float f = 0.f;
    for (int i = 0; i < TT; i++) {
        float y = g12[((long)(b * TT + i)) * 256 + 128 + c];
        f = fmaf(r, f, y);
        scanF[(b * TT + i) * DGC + c] = f;
    }
    float bk = 0.f;
    for (int i = TT - 1; i >= 0; i--) {
        float y = g12[((long)(b * TT + i)) * 256 + 128 + c];
        bk = fmaf(r, bk, y);
        float v = scanF[(b * TT + i) * DGC + c] + bk - y;
        v = (v >= 0.f) ? v : 0.01f * v;
        outx[((long)(b * TT + i)) * 256 + 128 + c] = v;
    }
}

__global__ void frame_kernel(const float* outx, const float* cls_w,
                             const float* cls_b, float* frame, float* out) {
    int warp = threadIdx.x >> 5, lane = threadIdx.x & 31;
    int row = blockIdx.x * 8 + warp;
    const float* xr = outx + (size_t)row * 256;
    float s = 0.f;
    for (int d = lane; d < 256; d += 32) {
        float sg = (d == 0) ? -1.0f : 1.0f;
        s += sg * xr[d] * cls_w[d];
    }
    for (int o = 16; o > 0; o >>= 1) s += __shfl_down_sync(0xffffffffu, s, o);
    if (lane == 0) {
        float v = 2.0f + 2.0f * s + cls_b[0];
        frame[row] = v;
        out[8 + row] = v;
    }
}

__global__ void clas_kernel(const float* frame, const int* seq_len, float* out) {
    __shared__ float s[TT];
    __shared__ float red[1024];
    const int b = blockIdx.x, tid = threadIdx.x;
    const int L = seq_len[b];
    for (int t = tid; t < TT; t += 1024)
        s[t] = (t < L) ? frame[b * TT + t] : -1e30f;
    __syncthreads();
    // bitonic sort, descending
    for (int size = 2; size <= TT; size <<= 1) {
        for (int stride = size >> 1; stride > 0; stride >>= 1) {
            for (int i = tid; i < TT; i += 1024) {
                int l = i ^ stride;
                if (l > i) {
                    float a = s[i], c = s[l];
                    bool desc = ((i & size) == 0);
                    if (desc ? (a < c) : (a > c)) { s[i] = c; s[l] = a; }
                }
            }
            __syncthreads();
        }
    }
    int k = L / 16 + 1;
    float ps = 0.f;
    for (int t = tid; t < k; t += 1024) ps += s[t];
    red[tid] = ps;
    __syncthreads();
    for (int st = 512; st > 0; st >>= 1) {
        if (tid < st) red[tid] += red[tid + st];
        __syncthreads();
    }
    if (tid == 0) {
        float m = red[0] / (float)k;
        out[b] = 1.0f / (1.0f + expf(-m));
    }
}

/* ---------------- host orchestration ---------------- */
extern "C" void kernel_launch(void* const* d_in, const int* in_sizes, int n_in,
                              void* d_out, int out_size) {
    const float* inputs = (const float*)d_in[0];
    const int*   seq    = (const int*)d_in[1];
    const float* w1     = (const float*)d_in[2];
    const float* b1     = (const float*)d_in[3];
    const float* w2     = (const float*)d_in[4];
    const float* b2     = (const float*)d_in[5];
    const float* gw1    = (const float*)d_in[6];
    const float* gw2    = (const float*)d_in[7];
    const float* cls_w  = (const float*)d_in[8];
    const float* cls_b  = (const float*)d_in[9];
    float* out = (float*)d_out;

    float *y1, *xv2, *proj, *qproj, *gwT, *g12, *g1T, *E, *denom, *outx, *frame, *scanF;
    cudaGetSymbolAddress((void**)&y1,    g_y1);
    cudaGetSymbolAddress((void**)&xv2,   g_xv2);
    cudaGetSymbolAddress((void**)&proj,  g_proj);
    cudaGetSymbolAddress((void**)&qproj, g_qproj);
    cudaGetSymbolAddress((void**)&gwT,   g_gwT);
    cudaGetSymbolAddress((void**)&g12,   g_g12);
    cudaGetSymbolAddress((void**)&g1T,   g_g1T);
    cudaGetSymbolAddress((void**)&E,     g_E);
    cudaGetSymbolAddress((void**)&denom, g_denom);
    cudaGetSymbolAddress((void**)&outx,  g_outx);
    cudaGetSymbolAddress((void**)&frame, g_frame);
    cudaGetSymbolAddress((void**)&scanF, g_scanF);

    // gw transpose + pad (independent of other work)
    prep_gwT<<<(256 * DHP) / 256, 256>>>(gw1, gw2, gwT);

    // GEMM1: y1 = leaky(inputs[:, :1024] @ w1^T + b1)   M=16384 N=512 K=1024
    {
        GemmP p = { inputs, w1, y1, DVC, IN_C, DVC, D1C, 0, 0, 0, b1, nullptr, nullptr };
        sgemm<0><<<dim3(D1C / 128, M_ROWS / 128, 1), 256>>>(p);
    }
    // GEMM2: xv2 = leaky(y1 @ w2^T + b2)   M=16384 N=128 K=512
    {
        GemmP p = { y1, w2, xv2, D1C, D1C, D1C, D2C, 0, 0, 0, b2, nullptr, nullptr };
        sgemm<0><<<dim3(1, M_ROWS / 128, 1), 256>>>(p);
    }
    // Lorentz expmap -> proj (and sign-flipped qproj), padded to 264
    proj_kernel<<<M_ROWS, 256>>>(xv2, inputs, proj, qproj);

    // g12 = proj @ [gw1 | gw2]   M=16384 N=256 K=264
    {
        GemmP p = { proj, gwT, g12, DHP, DHP, DHP, 256, 0, 0, 0, nullptr, nullptr, nullptr };
        sgemm<1><<<dim3(2, M_ROWS / 128, 1), 256>>>(p);
    }
    // transpose g1 per batch -> [128, T]
    transpose_g1<<<dim3(TT / 32, DGC / 32, BB), dim3(32, 8)>>>(g12, g1T);

    // similarity -> E[b,i,j] = (j<L) ? exp(thr) : 0     per-batch 2048x2048x264
    {
        GemmP p = { qproj, proj, E, DHP, DHP, DHP, TT,
                    (long)TT * DHP, (long)TT * DHP, (long)TT * TT,
                    nullptr, seq, nullptr };
        sgemm<2><<<dim3(TT / 128, TT / 128, BB), 256>>>(p);
    }
    // softmax denominators
    rowsum_kernel<<<M_ROWS, 256>>>(E, denom);

    // x1 = leaky((E/denom) @ g1), row-masked   per-batch 2048x128x2048
    {
        GemmP p = { E, g1T, outx, TT, TT, TT, 256,
                    (long)TT * TT, (long)DGC * TT, (long)TT * 256,
                    nullptr, seq, denom };
        sgemm<3><<<dim3(1, TT / 128, BB), 256>>>(p);
    }
    // x2 = leaky(disadj @ g2) via exponential scan -> outx cols 128..255
    scan_kernel<<<BB, DGC>>>(g12, scanF, outx);

    // frame_prob = 2 + 2*(signs*outx)·cls_w + cls_b ; also write to output
    frame_kernel<<<M_ROWS / 8, 256>>>(outx, cls_w, cls_b, frame, out);

    // MIL: top-k mean + sigmoid per batch
    clas_kernel<<<BB, 1024>>>(frame, seq, out);
}

// round 6
// speedup vs baseline: 2.2014x; 2.2014x over previous
#include <cuda_runtime.h>
#include <math.h>

#define BB 8
#define TT 2048
#define M_ROWS (BB*TT)   /* 16384 */
#define DVC 1024
#define DAC 128
#define IN_C 1152
#define D1C 512
#define D2C 128
#define DHP 264          /* 257 padded to mult of 8 */
#define DGC 128

typedef unsigned long long u64;

/* ---------------- scratch (static device globals; no allocs) ---------------- */
__device__ float g_y1[M_ROWS * D1C];        // 33.5 MB
__device__ float g_xv2[M_ROWS * D2C];       // 8.4 MB
__device__ float g_proj[M_ROWS * DHP];      // 17.3 MB
__device__ float g_qproj[M_ROWS * DHP];     // 17.3 MB
__device__ float g_gwT[256 * DHP];
__device__ float g_g12[M_ROWS * 256];
__device__ float g_g1T[BB * DGC * TT];
__device__ float g_E[(size_t)BB * TT * TT]; // 134 MB
__device__ float g_denom[M_ROWS];
__device__ float g_outx[M_ROWS * 256];
__device__ float g_frame[M_ROWS];

/* ---------------- packed f32x2 helpers (Blackwell FFMA2) ---------------- */
__device__ __forceinline__ void ffma2(u64 &d, u64 a, u64 b) {
    asm("fma.rn.f32x2 %0, %1, %2, %0;" : "+l"(d) : "l"(a), "l"(b));
}
__device__ __forceinline__ u64 pack2(float x) {
    u64 r; asm("mov.b64 %0, {%1, %1};" : "=l"(r) : "f"(x)); return r;
}
__device__ __forceinline__ float2 unpk(u64 v) {
    float2 r; asm("mov.b64 {%0, %1}, %2;" : "=f"(r.x), "=f"(r.y) : "l"(v)); return r;
}

/* ---------------- generic 128x128x8 SGEMM, C = A[M,K] * B[N,K]^T ------------ */
struct GemmP {
    const float* A; const float* Bm; float* C;
    int K, lda, ldb, ldc;
    long aS, bS, cS;            // per-blockIdx.z strides
    const float* bias;
    const int* seq;
    const float* denom;
};

// MODE 0: C = leaky(acc + bias[n])
// MODE 1: C = acc
// MODE 2: similarity epilogue -> E (col-masked exp(thr)), fast path for xy>1.03
// MODE 3: adj matmul epilogue -> leaky(acc/denom) row-masked
template <int MODE>
__global__ __launch_bounds__(256, 2) void sgemm(GemmP p) {
    __shared__ float As[2][8][128];
    __shared__ float Bs[2][8][128];
    const int z = blockIdx.z;
    const float* A  = p.A  + (long)z * p.aS;
    const float* Bm = p.Bm + (long)z * p.bS;
    float*       C  = p.C  + (long)z * p.cS;
    const int tid = threadIdx.x;
    const int tx = tid & 15, ty = tid >> 4;
    const int rowBase = blockIdx.y << 7;
    const int colBase = blockIdx.x << 7;
    const int lr = tid >> 1;
    const int lc = (tid & 1) << 2;
    const float* aPtr = A  + (long)(rowBase + lr) * p.lda + lc;
    const float* bPtr = Bm + (long)(colBase + lr) * p.ldb + lc;

    u64 acc[8][4];
#pragma unroll
    for (int i = 0; i < 8; i++)
#pragma unroll
        for (int j = 0; j < 4; j++) acc[i][j] = 0ULL;

    const int nk = p.K >> 3;
    // prologue: stage chunk 0
    float4 av = *(const float4*)(aPtr);
    float4 bv = *(const float4*)(bPtr);
    As[0][lc + 0][lr] = av.x; As[0][lc + 1][lr] = av.y;
    As[0][lc + 2][lr] = av.z; As[0][lc + 3][lr] = av.w;
    Bs[0][lc + 0][lr] = bv.x; Bs[0][lc + 1][lr] = bv.y;
    Bs[0][lc + 2][lr] = bv.z; Bs[0][lc + 3][lr] = bv.w;
    __syncthreads();

    for (int t = 0; t < nk; t++) {
        const int cur = t & 1;
        if (t + 1 < nk) {
            av = *(const float4*)(aPtr + ((t + 1) << 3));
            bv = *(const float4*)(bPtr + ((t + 1) << 3));
        }
#pragma unroll
        for (int kk = 0; kk < 8; kk++) {
            float4 a0 = *(const float4*)&As[cur][kk][ty << 3];
            float4 a1 = *(const float4*)&As[cur][kk][(ty << 3) + 4];
            ulonglong2 q0 = *(const ulonglong2*)&Bs[cur][kk][tx << 3];
            ulonglong2 q1 = *(const ulonglong2*)&Bs[cur][kk][(tx << 3) + 4];
            const u64 bb0 = q0.x, bb1 = q0.y, bb2 = q1.x, bb3 = q1.y;
            float aa[8] = {a0.x, a0.y, a0.z, a0.w, a1.x, a1.y, a1.z, a1.w};
#pragma unroll
            for (int i = 0; i < 8; i++) {
                u64 a2 = pack2(aa[i]);
                ffma2(acc[i][0], a2, bb0);
                ffma2(acc[i][1], a2, bb1);
                ffma2(acc[i][2], a2, bb2);
                ffma2(acc[i][3], a2, bb3);
            }
        }
        if (t + 1 < nk) {
            const int nxt = cur ^ 1;
            As[nxt][lc + 0][lr] = av.x; As[nxt][lc + 1][lr] = av.y;
            As[nxt][lc + 2][lr] = av.z; As[nxt][lc + 3][lr] = av.w;
            Bs[nxt][lc + 0][lr] = bv.x; Bs[nxt][lc + 1][lr] = bv.y;
            Bs[nxt][lc + 2][lr] = bv.z; Bs[nxt][lc + 3][lr] = bv.w;
            __syncthreads();
        }
    }

    const int L = (MODE >= 2) ? p.seq[z] : 0;
#pragma unroll
    for (int i = 0; i < 8; i++) {
        const int m = rowBase + (ty << 3) + i;
        float inv = 1.0f;
        if (MODE == 3) inv = 1.0f / p.denom[z * TT + m];
        float vals[8];
#pragma unroll
        for (int pq = 0; pq < 4; pq++) {
            float2 f = unpk(acc[i][pq]);
            vals[2 * pq] = f.x; vals[2 * pq + 1] = f.y;
        }
#pragma unroll
        for (int j8 = 0; j8 < 8; j8++) {
            const int n = colBase + (tx << 3) + j8;
            float v = vals[j8];
            if (MODE == 0) {
                v += p.bias[n];
                v = (v >= 0.f) ? v : 0.01f * v;
            } else if (MODE == 2) {
                if (n >= L) v = 0.f;
                else {
                    float xy = -v;
                    if (xy > 1.03f) {
                        v = 1.0f;   // x2 < 0.8 guaranteed -> thr=0 -> exp(0)=1 (bit-exact)
                    } else {
                        xy = fmaxf(xy, 1.0f);
                        float w  = xy + sqrtf(xy * xy - 1.0f + 1e-7f);
                        float x2v = 1.0f / w;
                        v = (x2v > 0.8f) ? expf(x2v) : 1.0f;
                    }
                }
            } else if (MODE == 3) {
                v *= inv;
                v = (v >= 0.f) ? v : 0.01f * v;
                if (m >= L) v = 0.f;
            }
            vals[j8] = v;
        }
        float4* dst = (float4*)&C[(long)m * p.ldc + colBase + (tx << 3)];
        dst[0] = make_float4(vals[0], vals[1], vals[2], vals[3]);
        dst[1] = make_float4(vals[4], vals[5], vals[6], vals[7]);
    }
}

/* ---------------- small kernels ---------------- */
__global__ void prep_gwT(const float* gw1, const float* gw2, float* gwT) {
    int idx = blockIdx.x * 256 + threadIdx.x;
    if (idx >= 256 * DHP) return;
    int r = idx / DHP, k = idx % DHP;
    float v = 0.f;
    if (k < 257) v = (r < 128) ? gw1[k * 128 + r] : gw2[k * 128 + (r - 128)];
    gwT[idx] = v;
}

__global__ void proj_kernel(const float* xv2, const float* inputs,
                            float* proj, float* qproj) {
    const int row = blockIdx.x;
    const int tid = threadIdx.x;  // 256
    float x = (tid < 128) ? xv2[row * 128 + tid]
                          : inputs[(long)row * IN_C + DVC + (tid - 128)];
    __shared__ float red[256];
    red[tid] = x * x;
    __syncthreads();
    for (int st = 128; st > 0; st >>= 1) {
        if (tid < st) red[tid] += red[tid + st];
        __syncthreads();
    }
    float nn = sqrtf(fmaxf(red[0], 1e-12f));
    float sh = sinhf(nn) / nn;
    float* pr = proj  + (long)row * DHP;
    float* qr = qproj + (long)row * DHP;
    float val = sh * x;
    pr[1 + tid] = val;
    qr[1 + tid] = val;
    if (tid == 0) { float ch = coshf(nn); pr[0] = ch; qr[0] = -ch; }
    if (tid < 7)  { pr[257 + tid] = 0.f; qr[257 + tid] = 0.f; }
}

__global__ void transpose_g1(const float* g12, float* g1T) {
    __shared__ float tile[32][33];
    int b = blockIdx.z;
    int t0 = blockIdx.x * 32, n0 = blockIdx.y * 32;
    for (int r = threadIdx.y; r < 32; r += 8)
        tile[r][threadIdx.x] = g12[((long)(b * TT + t0 + r)) * 256 + n0 + threadIdx.x];
    __syncthreads();
    for (int r = threadIdx.y; r < 32; r += 8)
        g1T[(long)b * DGC * TT + (long)(n0 + r) * TT + t0 + threadIdx.x] = tile[threadIdx.x][r];
}

__global__ void rowsum_kernel(const float* E, float* denom) {
    int row = blockIdx.x;
    const float4* e = (const float4*)(E + (size_t)row * TT);
    float s = 0.f;
    for (int j = threadIdx.x; j < TT / 4; j += 256) {
        float4 v = e[j];
        s += (v.x + v.y) + (v.z + v.w);
    }
    for (int o = 16; o > 0; o >>= 1) s += __shfl_down_sync(0xffffffffu, s, o);
    __shared__ float red[8];
    if ((threadIdx.x & 31) == 0) red[threadIdx.x >> 5] = s;
    __syncthreads();
    if (threadIdx.x == 0) {
        float t = 0.f;
#pragma unroll
        for (int w = 0; w < 8; w++) t += red[w];
        denom[row] = t;
    }
}

// disadj @ y via windowed forward+backward exponential scan.
// r^128 ~ 4e-21 -> truncation far below fp32 ulp.
#define SC 64
#define SHALO 128
__global__ void scan_kernel(const float* g12, float* outx) {
    const int b = blockIdx.x;          // 8
    const int c = blockIdx.y;          // 32 chunks of 64 rows
    const int ch = threadIdx.x;        // 128 channels
    const float r = 0.69220062755534635f;  // exp(-exp(-1))
    __shared__ float sf[SC][DGC];
    const int s = c * SC;
    int i0 = s - SHALO; if (i0 < 0) i0 = 0;
    float f = 0.f;
    for (int i = i0; i < s + SC; i++) {
        float y = g12[((long)(b * TT + i)) * 256 + 128 + ch];
        f = fmaf(r, f, y);
        if (i >= s) sf[i - s][ch] = f;
    }
    int i1 = s + SC + SHALO; if (i1 > TT) i1 = TT;
    float bk = 0.f;
    for (int i = i1 - 1; i >= s; i--) {
        float y = g12[((long)(b * TT + i)) * 256 + 128 + ch];
        bk = fmaf(r, bk, y);
        if (i < s + SC) {
            float v = sf[i - s][ch] + bk - y;
            v = (v >= 0.f) ? v : 0.01f * v;
            outx[((long)(b * TT + i)) * 256 + 128 + ch] = v;
        }
    }
}

__global__ void frame_kernel(const float* outx, const float* cls_w,
                             const float* cls_b, float* frame, float* out) {
    int warp = threadIdx.x >> 5, lane = threadIdx.x & 31;
    int row = blockIdx.x * 8 + warp;
    const float* xr = outx + (size_t)row * 256;
    float s = 0.f;
    for (int d = lane; d < 256; d += 32) {
        float sg = (d == 0) ? -1.0f : 1.0f;
        s += sg * xr[d] * cls_w[d];
    }
    for (int o = 16; o > 0; o >>= 1) s += __shfl_down_sync(0xffffffffu, s, o);
    if (lane == 0) {
        float v = 2.0f + 2.0f * s + cls_b[0];
        frame[row] = v;
        out[8 + row] = v;
    }
}

__global__ void clas_kernel(const float* frame, const int* seq_len, float* out) {
    __shared__ float s[TT];
    __shared__ float red[1024];
    const int b = blockIdx.x, tid = threadIdx.x;
    const int L = seq_len[b];
    for (int t = tid; t < TT; t += 1024)
        s[t] = (t < L) ? frame[b * TT + t] : -1e30f;
    __syncthreads();
    for (int size = 2; size <= TT; size <<= 1) {
        for (int stride = size >> 1; stride > 0; stride >>= 1) {
            for (int i = tid; i < TT; i += 1024) {
                int l = i ^ stride;
                if (l > i) {
                    float a = s[i], c = s[l];
                    bool desc = ((i & size) == 0);
                    if (desc ? (a < c) : (a > c)) { s[i] = c; s[l] = a; }
                }
            }
            __syncthreads();
        }
    }
    int k = L / 16 + 1;
    float ps = 0.f;
    for (int t = tid; t < k; t += 1024) ps += s[t];
    red[tid] = ps;
    __syncthreads();
    for (int st = 512; st > 0; st >>= 1) {
        if (tid < st) red[tid] += red[tid + st];
        __syncthreads();
    }
    if (tid == 0) {
        float m = red[0] / (float)k;
        out[b] = 1.0f / (1.0f + expf(-m));
    }
}

/* ---------------- host orchestration ---------------- */
extern "C" void kernel_launch(void* const* d_in, const int* in_sizes, int n_in,
                              void* d_out, int out_size) {
    const float* inputs = (const float*)d_in[0];
    const int*   seq    = (const int*)d_in[1];
    const float* w1     = (const float*)d_in[2];
    const float* b1     = (const float*)d_in[3];
    const float* w2     = (const float*)d_in[4];
    const float* b2     = (const float*)d_in[5];
    const float* gw1    = (const float*)d_in[6];
    const float* gw2    = (const float*)d_in[7];
    const float* cls_w  = (const float*)d_in[8];
    const float* cls_b  = (const float*)d_in[9];
    float* out = (float*)d_out;

    float *y1, *xv2, *proj, *qproj, *gwT, *g12, *g1T, *E, *denom, *outx, *frame;
    cudaGetSymbolAddress((void**)&y1,    g_y1);
    cudaGetSymbolAddress((void**)&xv2,   g_xv2);
    cudaGetSymbolAddress((void**)&proj,  g_proj);
    cudaGetSymbolAddress((void**)&qproj, g_qproj);
    cudaGetSymbolAddress((void**)&gwT,   g_gwT);
    cudaGetSymbolAddress((void**)&g12,   g_g12);
    cudaGetSymbolAddress((void**)&g1T,   g_g1T);
    cudaGetSymbolAddress((void**)&E,     g_E);
    cudaGetSymbolAddress((void**)&denom, g_denom);
    cudaGetSymbolAddress((void**)&outx,  g_outx);
    cudaGetSymbolAddress((void**)&frame, g_frame);

    prep_gwT<<<(256 * DHP + 255) / 256, 256>>>(gw1, gw2, gwT);

    // GEMM1: y1 = leaky(inputs[:, :1024] @ w1^T + b1)   M=16384 N=512 K=1024
    {
        GemmP p = { inputs, w1, y1, DVC, IN_C, DVC, D1C, 0, 0, 0, b1, nullptr, nullptr };
        sgemm<0><<<dim3(D1C / 128, M_ROWS / 128, 1), 256>>>(p);
    }
    // GEMM2: xv2 = leaky(y1 @ w2^T + b2)   M=16384 N=128 K=512
    {
        GemmP p = { y1, w2, xv2, D1C, D1C, D1C, D2C, 0, 0, 0, b2, nullptr, nullptr };
        sgemm<0><<<dim3(1, M_ROWS / 128, 1), 256>>>(p);
    }
    proj_kernel<<<M_ROWS, 256>>>(xv2, inputs, proj, qproj);

    // g12 = proj @ [gw1 | gw2]   M=16384 N=256 K=264
    {
        GemmP p = { proj, gwT, g12, DHP, DHP, DHP, 256, 0, 0, 0, nullptr, nullptr, nullptr };
        sgemm<1><<<dim3(2, M_ROWS / 128, 1), 256>>>(p);
    }
    transpose_g1<<<dim3(TT / 32, DGC / 32, BB), dim3(32, 8)>>>(g12, g1T);

    // similarity -> E   per-batch 2048x2048x264
    {
        GemmP p = { qproj, proj, E, DHP, DHP, DHP, TT,
                    (long)TT * DHP, (long)TT * DHP, (long)TT * TT,
                    nullptr, seq, nullptr };
        sgemm<2><<<dim3(TT / 128, TT / 128, BB), 256>>>(p);
    }
    rowsum_kernel<<<M_ROWS, 256>>>(E, denom);

    // x1 = leaky((E/denom) @ g1), row-masked   per-batch 2048x128x2048
    {
        GemmP p = { E, g1T, outx, TT, TT, TT, 256,
                    (long)TT * TT, (long)DGC * TT, (long)TT * 256,
                    nullptr, seq, denom };
        sgemm<3><<<dim3(1, TT / 128, BB), 256>>>(p);
    }
    // x2 = leaky(disadj @ g2) via windowed exponential scan
    scan_kernel<<<dim3(BB, TT / SC), DGC>>>(g12, outx);

    frame_kernel<<<M_ROWS / 8, 256>>>(outx, cls_w, cls_b, frame, out);
    clas_kernel<<<BB, 1024>>>(frame, seq, out);
}

// round 8
// speedup vs baseline: 2.3241x; 1.0557x over previous
#include <cuda_runtime.h>
#include <math.h>

#define BB 8
#define TT 2048
#define M_ROWS (BB*TT)   /* 16384 */
#define DVC 1024
#define DAC 128
#define IN_C 1152
#define D1C 512
#define D2C 128
#define DHP 264          /* 257 padded to mult of 8 */
#define DGC 128

typedef unsigned long long u64;

/* ---------------- scratch (static device globals; no allocs) ---------------- */
__device__ float g_y1[M_ROWS * D1C];
__device__ float g_xv2[M_ROWS * D2C];
__device__ float g_proj[M_ROWS * DHP];
__device__ float g_qproj[M_ROWS * DHP];
__device__ float g_gwT[256 * DHP];
__device__ float g_g12[M_ROWS * 256];
__device__ float g_g1T[BB * DGC * TT];
__device__ float g_E[(size_t)BB * TT * TT]; // 134 MB
__device__ float g_denom[M_ROWS];
__device__ float g_x1p[2 * M_ROWS * DGC];   // split-K raw partials
__device__ float g_x2[M_ROWS * DGC];
__device__ float g_frame[M_ROWS];

/* ---------------- packed f32x2 helpers (Blackwell FFMA2) ---------------- */
__device__ __forceinline__ void ffma2(u64 &d, u64 a, u64 b) {
    asm("fma.rn.f32x2 %0, %1, %2, %0;" : "+l"(d) : "l"(a), "l"(b));
}
__device__ __forceinline__ u64 pack2(float x) {
    u64 r; asm("mov.b64 %0, {%1, %1};" : "=l"(r) : "f"(x)); return r;
}
__device__ __forceinline__ float2 unpk(u64 v) {
    float2 r; asm("mov.b64 {%0, %1}, %2;" : "=f"(r.x), "=f"(r.y) : "l"(v)); return r;
}

/* ---------------- generic 128x128x8 SGEMM, C = A[M,K] * B[N,K]^T ------------ */
struct GemmP {
    const float* A; const float* Bm; float* C;
    int K, lda, ldb, ldc;
    long aS, bS, cS;            // per-blockIdx.z strides
    long splitStride;           // MODE3: offset between K-split partial buffers
    const float* bias;
    const int* seq;
    float* denom;               // MODE2: atomic row-sum output
};

// MODE 0: C = leaky(acc + bias[n])
// MODE 1: C = acc
// MODE 2: similarity -> E (tile-skipped by seq_len) + fused row-sum atomics
// MODE 3: raw adj matmul partials, split-K over gridDim.x, K clamped to ceil8(L)
template <int MODE>
__global__ __launch_bounds__(256, 2) void sgemm(GemmP p) {
    const int z = blockIdx.z;
    const int rowBase = blockIdx.y << 7;
    int colBase, split;
    if (MODE == 3) { colBase = 0; split = blockIdx.x; }
    else           { colBase = blockIdx.x << 7; split = 0; }

    int L = 0;
    if (MODE >= 2) L = p.seq[z];
    if (MODE == 2 && (rowBase >= L || colBase >= L)) return;   // tile never read
    if (MODE == 3 && rowBase >= L) return;                     // output rows masked

    int k_begin = 0, k_end = p.K >> 3;
    if (MODE == 3) {
        const int nk_eff = (L + 7) >> 3;      // E cols >= ceil8(L) are zero
        const int half   = (nk_eff + 1) >> 1;
        k_begin = split ? half : 0;
        k_end   = split ? nk_eff : half;
    }

    __shared__ float As[2][8][128];
    __shared__ float Bs[2][8][128];
    const float* A  = p.A  + (long)z * p.aS;
    const float* Bm = p.Bm + (long)z * p.bS;
    float*       C  = p.C  + (long)z * p.cS + (long)split * p.splitStride;
    const int tid = threadIdx.x;
    const int tx = tid & 15, ty = tid >> 4;
    const int lr = tid >> 1;
    const int lc = (tid & 1) << 2;
    const float* aPtr = A  + (long)(rowBase + lr) * p.lda + lc;
    const float* bPtr = Bm + (long)(colBase + lr) * p.ldb + lc;

    u64 acc[8][4];
#pragma unroll
    for (int i = 0; i < 8; i++)
#pragma unroll
        for (int j = 0; j < 4; j++) acc[i][j] = 0ULL;

    // prologue: stage first chunk
    float4 av = *(const float4*)(aPtr + (k_begin << 3));
    float4 bv = *(const float4*)(bPtr + (k_begin << 3));
    As[0][lc + 0][lr] = av.x; As[0][lc + 1][lr] = av.y;
    As[0][lc + 2][lr] = av.z; As[0][lc + 3][lr] = av.w;
    Bs[0][lc + 0][lr] = bv.x; Bs[0][lc + 1][lr] = bv.y;
    Bs[0][lc + 2][lr] = bv.z; Bs[0][lc + 3][lr] = bv.w;
    __syncthreads();

    for (int t = k_begin; t < k_end; t++) {
        const int cur = (t - k_begin) & 1;
        if (t + 1 < k_end) {
            av = *(const float4*)(aPtr + ((t + 1) << 3));
            bv = *(const float4*)(bPtr + ((t + 1) << 3));
        }
#pragma unroll
        for (int kk = 0; kk < 8; kk++) {
            float4 a0 = *(const float4*)&As[cur][kk][ty << 3];
            float4 a1 = *(const float4*)&As[cur][kk][(ty << 3) + 4];
            ulonglong2 q0 = *(const ulonglong2*)&Bs[cur][kk][tx << 3];
            ulonglong2 q1 = *(const ulonglong2*)&Bs[cur][kk][(tx << 3) + 4];
            const u64 bb0 = q0.x, bb1 = q0.y, bb2 = q1.x, bb3 = q1.y;
            float aa[8] = {a0.x, a0.y, a0.z, a0.w, a1.x, a1.y, a1.z, a1.w};
#pragma unroll
            for (int i = 0; i < 8; i++) {
                u64 a2 = pack2(aa[i]);
                ffma2(acc[i][0], a2, bb0);
                ffma2(acc[i][1], a2, bb1);
                ffma2(acc[i][2], a2, bb2);
                ffma2(acc[i][3], a2, bb3);
            }
        }
        if (t + 1 < k_end) {
            const int nxt = cur ^ 1;
            As[nxt][lc + 0][lr] = av.x; As[nxt][lc + 1][lr] = av.y;
            As[nxt][lc + 2][lr] = av.z; As[nxt][lc + 3][lr] = av.w;
            Bs[nxt][lc + 0][lr] = bv.x; Bs[nxt][lc + 1][lr] = bv.y;
            Bs[nxt][lc + 2][lr] = bv.z; Bs[nxt][lc + 3][lr] = bv.w;
            __syncthreads();
        }
    }

#pragma unroll
    for (int i = 0; i < 8; i++) {
        const int m = rowBase + (ty << 3) + i;
        float vals[8];
#pragma unroll
        for (int pq = 0; pq < 4; pq++) {
            float2 f = unpk(acc[i][pq]);
            vals[2 * pq] = f.x; vals[2 * pq + 1] = f.y;
        }
#pragma unroll
        for (int j8 = 0; j8 < 8; j8++) {
            const int n = colBase + (tx << 3) + j8;
            float v = vals[j8];
            if (MODE == 0) {
                v += p.bias[n];
                v = (v >= 0.f) ? v : 0.01f * v;
            } else if (MODE == 2) {
                if (n >= L) v = 0.f;
                else {
                    float xy = -v;
                    if (xy > 1.03f) {
                        v = 1.0f;   // x2 < 0.8 guaranteed -> thr=0 -> exp(0)=1
                    } else {
                        xy = fmaxf(xy, 1.0f);
                        float w  = xy + sqrtf(xy * xy - 1.0f + 1e-7f);
                        float x2v = 1.0f / w;
                        v = (x2v > 0.8f) ? expf(x2v) : 1.0f;
                    }
                }
            }
            // MODE 1 / MODE 3: raw accumulator out
            vals[j8] = v;
        }
        if (MODE == 2) {
            // fused softmax denominator: reduce 8 local cols, then across the
            // 16 tx lanes (contiguous half-warp for fixed ty), atomic per col-tile
            float rp = ((vals[0] + vals[1]) + (vals[2] + vals[3])) +
                       ((vals[4] + vals[5]) + (vals[6] + vals[7]));
            rp += __shfl_down_sync(0xffffffffu, rp, 8, 16);
            rp += __shfl_down_sync(0xffffffffu, rp, 4, 16);
            rp += __shfl_down_sync(0xffffffffu, rp, 2, 16);
            rp += __shfl_down_sync(0xffffffffu, rp, 1, 16);
            if (tx == 0) atomicAdd(&p.denom[z * TT + m], rp);
        }
        float4* dst = (float4*)&C[(long)m * p.ldc + colBase + (tx << 3)];
        dst[0] = make_float4(vals[0], vals[1], vals[2], vals[3]);
        dst[1] = make_float4(vals[4], vals[5], vals[6], vals[7]);
    }
}

/* ---------------- small kernels ---------------- */
__global__ void zero_denom(float* denom) {
    denom[blockIdx.x * 1024 + threadIdx.x] = 0.f;
}

__global__ void prep_gwT(const float* gw1, const float* gw2, float* gwT) {
    int idx = blockIdx.x * 256 + threadIdx.x;
    if (idx >= 256 * DHP) return;
    int r = idx / DHP, k = idx % DHP;
    float v = 0.f;
    if (k < 257) v = (r < 128) ? gw1[k * 128 + r] : gw2[k * 128 + (r - 128)];
    gwT[idx] = v;
}

__global__ void proj_kernel(const float* xv2, const float* inputs,
                            float* proj, float* qproj) {
    const int row = blockIdx.x;
    const int tid = threadIdx.x;  // 256
    float x = (tid < 128) ? xv2[row * 128 + tid]
                          : inputs[(long)row * IN_C + DVC + (tid - 128)];
    __shared__ float red[256];
    red[tid] = x * x;
    __syncthreads();
    for (int st = 128; st > 0; st >>= 1) {
        if (tid < st) red[tid] += red[tid + st];
        __syncthreads();
    }
    float nn = sqrtf(fmaxf(red[0], 1e-12f));
    float sh = sinhf(nn) / nn;
    float* pr = proj  + (long)row * DHP;
    float* qr = qproj + (long)row * DHP;
    float val = sh * x;
    pr[1 + tid] = val;
    qr[1 + tid] = val;
    if (tid == 0) { float ch = coshf(nn); pr[0] = ch; qr[0] = -ch; }
    if (tid < 7)  { pr[257 + tid] = 0.f; qr[257 + tid] = 0.f; }
}

__global__ void transpose_g1(const float* g12, float* g1T) {
    __shared__ float tile[32][33];
    int b = blockIdx.z;
    int t0 = blockIdx.x * 32, n0 = blockIdx.y * 32;
    for (int r = threadIdx.y; r < 32; r += 8)
        tile[r][threadIdx.x] = g12[((long)(b * TT + t0 + r)) * 256 + n0 + threadIdx.x];
    __syncthreads();
    for (int r = threadIdx.y; r < 32; r += 8)
        g1T[(long)b * DGC * TT + (long)(n0 + r) * TT + t0 + threadIdx.x] = tile[threadIdx.x][r];
}

// disadj @ y via windowed forward+backward exponential scan (r^128 ~ 4e-21)
#define SC 64
#define SHALO 128
__global__ void scan_kernel(const float* g12, float* x2) {
    const int b = blockIdx.x;
    const int c = blockIdx.y;
    const int ch = threadIdx.x;        // 128 channels
    const float r = 0.69220062755534635f;  // exp(-exp(-1))
    __shared__ float sf[SC][DGC];
    const int s = c * SC;
    int i0 = s - SHALO; if (i0 < 0) i0 = 0;
    float f = 0.f;
    for (int i = i0; i < s + SC; i++) {
        float y = g12[((long)(b * TT + i)) * 256 + 128 + ch];
        f = fmaf(r, f, y);
        if (i >= s) sf[i - s][ch] = f;
    }
    int i1 = s + SC + SHALO; if (i1 > TT) i1 = TT;
    float bk = 0.f;
    for (int i = i1 - 1; i >= s; i--) {
        float y = g12[((long)(b * TT + i)) * 256 + 128 + ch];
        bk = fmaf(r, bk, y);
        if (i < s + SC) {
            float v = sf[i - s][ch] + bk - y;
            v = (v >= 0.f) ? v : 0.01f * v;
            x2[((long)(b * TT + i)) * DGC + ch] = v;
        }
    }
}

__global__ void frame_kernel(const float* x1p, const float* x2,
                             const float* denom, const int* seq,
                             const float* cls_w, const float* cls_b,
                             float* frame, float* out) {
    int warp = threadIdx.x >> 5, lane = threadIdx.x & 31;
    int row = blockIdx.x * 8 + warp;
    const int b = row >> 11;           // row / TT
    const int m = row & (TT - 1);
    const int L = seq[b];
    float s = 0.f;
    if (m < L) {
        float inv = 1.0f / denom[row];
        const float* p0 = x1p + (size_t)row * DGC;
        const float* p1 = p0 + (size_t)M_ROWS * DGC;
        for (int d = lane; d < DGC; d += 32) {
            float v = (p0[d] + p1[d]) * inv;
            v = (v >= 0.f) ? v : 0.01f * v;
            float sg = (d == 0) ? -1.0f : 1.0f;
            s += sg * v * cls_w[d];
        }
    }
    const float* xr2 = x2 + (size_t)row * DGC;
    for (int d = lane; d < DGC; d += 32)
        s += xr2[d] * cls_w[DGC + d];
    for (int o = 16; o > 0; o >>= 1) s += __shfl_down_sync(0xffffffffu, s, o);
    if (lane == 0) {
        float v = 2.0f + 2.0f * s + cls_b[0];
        frame[row] = v;
        out[8 + row] = v;
    }
}

__global__ void clas_kernel(const float* frame, const int* seq_len, float* out) {
    __shared__ float s[TT];
    __shared__ float red[1024];
    const int b = blockIdx.x, tid = threadIdx.x;
    const int L = seq_len[b];
    for (int t = tid; t < TT; t += 1024)
        s[t] = (t < L) ? frame[b * TT + t] : -1e30f;
    __syncthreads();
    for (int size = 2; size <= TT; size <<= 1) {
        for (int stride = size >> 1; stride > 0; stride >>= 1) {
            for (int i = tid; i < TT; i += 1024) {
                int l = i ^ stride;
                if (l > i) {
                    float a = s[i], c = s[l];
                    bool desc = ((i & size) == 0);
                    if (desc ? (a < c) : (a > c)) { s[i] = c; s[l] = a; }
                }
            }
            __syncthreads();
        }
    }
    int k = L / 16 + 1;
    float ps = 0.f;
    for (int t = tid; t < k; t += 1024) ps += s[t];
    red[tid] = ps;
    __syncthreads();
    for (int st = 512; st > 0; st >>= 1) {
        if (tid < st) red[tid] += red[tid + st];
        __syncthreads();
    }
    if (tid == 0) {
        float m = red[0] / (float)k;
        out[b] = 1.0f / (1.0f + expf(-m));
    }
}

/* ---------------- host orchestration ---------------- */
extern "C" void kernel_launch(void* const* d_in, const int* in_sizes, int n_in,
                              void* d_out, int out_size) {
    const float* inputs = (const float*)d_in[0];
    const int*   seq    = (const int*)d_in[1];
    const float* w1     = (const float*)d_in[2];
    const float* b1     = (const float*)d_in[3];
    const float* w2     = (const float*)d_in[4];
    const float* b2     = (const float*)d_in[5];
    const float* gw1    = (const float*)d_in[6];
    const float* gw2    = (const float*)d_in[7];
    const float* cls_w  = (const float*)d_in[8];
    const float* cls_b  = (const float*)d_in[9];
    float* out = (float*)d_out;

    float *y1, *xv2, *proj, *qproj, *gwT, *g12, *g1T, *E, *denom, *x1p, *x2, *frame;
    cudaGetSymbolAddress((void**)&y1,    g_y1);
    cudaGetSymbolAddress((void**)&xv2,   g_xv2);
    cudaGetSymbolAddress((void**)&proj,  g_proj);
    cudaGetSymbolAddress((void**)&qproj, g_qproj);
    cudaGetSymbolAddress((void**)&gwT,   g_gwT);
    cudaGetSymbolAddress((void**)&g12,   g_g12);
    cudaGetSymbolAddress((void**)&g1T,   g_g1T);
    cudaGetSymbolAddress((void**)&E,     g_E);
    cudaGetSymbolAddress((void**)&denom, g_denom);
    cudaGetSymbolAddress((void**)&x1p,   g_x1p);
    cudaGetSymbolAddress((void**)&x2,    g_x2);
    cudaGetSymbolAddress((void**)&frame, g_frame);

    zero_denom<<<M_ROWS / 1024, 1024>>>(denom);
    prep_gwT<<<(256 * DHP + 255) / 256, 256>>>(gw1, gw2, gwT);

    // GEMM1: y1 = leaky(inputs[:, :1024] @ w1^T + b1)   M=16384 N=512 K=1024
    {
        GemmP p = { inputs, w1, y1, DVC, IN_C, DVC, D1C, 0, 0, 0, 0, b1, nullptr, nullptr };
        sgemm<0><<<dim3(D1C / 128, M_ROWS / 128, 1), 256>>>(p);
    }
    // GEMM2: xv2 = leaky(y1 @ w2^T + b2)   M=16384 N=128 K=512
    {
        GemmP p = { y1, w2, xv2, D1C, D1C, D1C, D2C, 0, 0, 0, 0, b2, nullptr, nullptr };
        sgemm<0><<<dim3(1, M_ROWS / 128, 1), 256>>>(p);
    }
    proj_kernel<<<M_ROWS, 256>>>(xv2, inputs, proj, qproj);

    // g12 = proj @ [gw1 | gw2]   M=16384 N=256 K=264
    {
        GemmP p = { proj, gwT, g12, DHP, DHP, DHP, 256, 0, 0, 0, 0, nullptr, nullptr, nullptr };
        sgemm<1><<<dim3(2, M_ROWS / 128, 1), 256>>>(p);
    }
    transpose_g1<<<dim3(TT / 32, DGC / 32, BB), dim3(32, 8)>>>(g12, g1T);

    // similarity -> E (tile-skipped) + fused denom atomics
    {
        GemmP p = { qproj, proj, E, DHP, DHP, DHP, TT,
                    (long)TT * DHP, (long)TT * DHP, (long)TT * TT, 0,
                    nullptr, seq, denom };
        sgemm<2><<<dim3(TT / 128, TT / 128, BB), 256>>>(p);
    }
    // x1 raw partials = E @ g1T, split-K(2), K clamped to ceil8(L)
    {
        GemmP p = { E, g1T, x1p, TT, TT, TT, DGC,
                    (long)TT * TT, (long)DGC * TT, (long)TT * DGC,
                    (long)M_ROWS * DGC, nullptr, seq, nullptr };
        sgemm<3><<<dim3(2, TT / 128, BB), 256>>>(p);
    }
    // x2 = leaky(disadj @ g2) via windowed exponential scan
    scan_kernel<<<dim3(BB, TT / SC), DGC>>>(g12, x2);

    // frame_prob: combine split-K partials, /denom, leaky, classifier dot
    frame_kernel<<<M_ROWS / 8, 256>>>(x1p, x2, denom, seq, cls_w, cls_b, frame, out);
    clas_kernel<<<BB, 1024>>>(frame, seq, out);
}